// round 1
// baseline (speedup 1.0000x reference)
#include <cuda_runtime.h>
#include <cstdint>

#define NN 200000
#define KK 27
#define PP 400000
#define CIN 32
#define CMID 64
#define COUT 32

// Scratch: intermediate h [N, CMID] (51.2 MB) — device global, no allocation.
__device__ __align__(16) float g_h[(size_t)NN * CMID];
__device__ int g_is64;

// ---------------------------------------------------------------------------
// Index-width detection: jax may have emitted int32 despite the int64 request.
// If the buffer is int64 (little-endian, values < 2^31), every odd 32-bit word
// of the first 64 entries is zero. If it's int32, those words are random
// indices in [0, 200000) — P(all 64 zero) ~ 0.
// ---------------------------------------------------------------------------
__global__ void detect_idx_kernel(const void* idx) {
    const unsigned int* w = (const unsigned int*)idx;
    int is64 = 1;
    #pragma unroll 1
    for (int i = 0; i < 64; i++) {
        if (w[2 * i + 1] != 0u) { is64 = 0; break; }
    }
    g_is64 = is64;
}

__device__ __forceinline__ long long ld_idx(const void* p, long long i, int is64) {
    if (is64) return ((const long long*)p)[i];
    return (long long)((const int*)p)[i];
}

// ---------------------------------------------------------------------------
// Layer 1: h[out] += (feats[in] @ W_in[k]) for valid pairs.  Warp per pair.
// Lane l holds feats[in][l]; broadcé via shfl; lane l produces outputs
// d = 2l, 2l+1  -> one red.global.add.v2.f32 per lane.
// ---------------------------------------------------------------------------
__global__ void __launch_bounds__(256) conv1_kernel(
    const float* __restrict__ feats,
    const void* __restrict__ in_idx, const void* __restrict__ out_idx,
    const float* __restrict__ mask,
    const float* __restrict__ W_in)
{
    __shared__ float2 Wsm[CIN * 32];  // [c][j] = (W[c][2j], W[c][2j+1]) : 8 KB
    const int k = blockIdx.y;
    const int is64 = g_is64;

    const float* Wk = W_in + (size_t)k * CIN * CMID;
    for (int i = threadIdx.x; i < CIN * 32; i += blockDim.x)
        Wsm[i] = ((const float2*)Wk)[i];
    __syncthreads();

    const int lane = threadIdx.x & 31;
    const int warp = (blockIdx.x * blockDim.x + threadIdx.x) >> 5;
    const int wstride = (gridDim.x * blockDim.x) >> 5;
    const long long base = (long long)k * PP;

    for (int p = warp; p < PP; p += wstride) {
        const float m = mask[base + p];          // warp-uniform broadcast load
        if (m <= 0.5f) continue;                 // warp-uniform predicate
        const long long in  = ld_idx(in_idx,  base + p, is64);
        const long long out = ld_idx(out_idx, base + p, is64);

        const float x = feats[in * CIN + lane];  // coalesced 128B gather
        float2 acc = make_float2(0.f, 0.f);
        #pragma unroll
        for (int c = 0; c < CIN; c++) {
            const float xc = __shfl_sync(0xffffffffu, x, c);
            const float2 w = Wsm[c * 32 + lane];
            acc.x += xc * w.x;
            acc.y += xc * w.y;
        }
        float* dst = g_h + out * CMID + 2 * lane;  // 8B-aligned
        asm volatile("red.global.add.v2.f32 [%0], {%1, %2};"
                     :: "l"(dst), "f"(acc.x), "f"(acc.y) : "memory");
    }
}

// ---------------------------------------------------------------------------
// ReLU in place over h.
// ---------------------------------------------------------------------------
__global__ void relu_kernel() {
    const size_t n4 = (size_t)NN * CMID / 4;
    float4* h4 = (float4*)g_h;
    for (size_t i = (size_t)blockIdx.x * blockDim.x + threadIdx.x; i < n4;
         i += (size_t)gridDim.x * blockDim.x) {
        float4 v = h4[i];
        v.x = fmaxf(v.x, 0.f); v.y = fmaxf(v.y, 0.f);
        v.z = fmaxf(v.z, 0.f); v.w = fmaxf(v.w, 0.f);
        h4[i] = v;
    }
}

// ---------------------------------------------------------------------------
// Layer 2: out[o] += (h[in] @ W_out[k]).  Warp per pair; lane l holds
// h[in][l] and h[in][32+l]; lane l produces output channel l (scalar red).
// ---------------------------------------------------------------------------
__global__ void __launch_bounds__(256) conv2_kernel(
    const void* __restrict__ in_idx, const void* __restrict__ out_idx,
    const float* __restrict__ mask,
    const float* __restrict__ W_out,
    float* __restrict__ outp)
{
    __shared__ float Wsm[CMID * COUT];  // [c][d] linear : 8 KB
    const int k = blockIdx.y;
    const int is64 = g_is64;

    const float* Wk = W_out + (size_t)k * CMID * COUT;
    for (int i = threadIdx.x; i < CMID * COUT / 4; i += blockDim.x)
        ((float4*)Wsm)[i] = ((const float4*)Wk)[i];
    __syncthreads();

    const int lane = threadIdx.x & 31;
    const int warp = (blockIdx.x * blockDim.x + threadIdx.x) >> 5;
    const int wstride = (gridDim.x * blockDim.x) >> 5;
    const long long base = (long long)k * PP;

    for (int p = warp; p < PP; p += wstride) {
        const float m = mask[base + p];
        if (m <= 0.5f) continue;
        const long long in  = ld_idx(in_idx,  base + p, is64);
        const long long out = ld_idx(out_idx, base + p, is64);

        const float x0 = g_h[in * CMID + lane];
        const float x1 = g_h[in * CMID + 32 + lane];
        float acc = 0.f;
        #pragma unroll
        for (int c = 0; c < 32; c++) {
            const float xc = __shfl_sync(0xffffffffu, x0, c);
            acc += xc * Wsm[c * COUT + lane];
        }
        #pragma unroll
        for (int c = 0; c < 32; c++) {
            const float xc = __shfl_sync(0xffffffffu, x1, c);
            acc += xc * Wsm[(32 + c) * COUT + lane];
        }
        atomicAdd(outp + out * COUT + lane, acc);  // -> RED.E.ADD.F32
    }
}

// ---------------------------------------------------------------------------
// Launch
// ---------------------------------------------------------------------------
extern "C" void kernel_launch(void* const* d_in, const int* in_sizes, int n_in,
                              void* d_out, int out_size) {
    (void)in_sizes; (void)n_in;
    const float* feats   = (const float*)d_in[0];
    const void*  in_idx  = d_in[1];
    const void*  out_idx = d_in[2];
    const float* mask    = (const float*)d_in[3];
    const float* W_in    = (const float*)d_in[4];
    const float* W_out   = (const float*)d_in[5];
    float* outp = (float*)d_out;

    void* h_ptr = nullptr;
    cudaGetSymbolAddress(&h_ptr, g_h);

    detect_idx_kernel<<<1, 1>>>(in_idx);
    cudaMemsetAsync(h_ptr, 0, (size_t)NN * CMID * sizeof(float));
    cudaMemsetAsync(d_out, 0, (size_t)out_size * sizeof(float));

    dim3 grid1(192, KK);
    conv1_kernel<<<grid1, 256>>>(feats, in_idx, out_idx, mask, W_in);

    relu_kernel<<<2048, 256>>>();

    dim3 grid2(192, KK);
    conv2_kernel<<<grid2, 256>>>(in_idx, out_idx, mask, W_out, outp);
}

// round 4
// speedup vs baseline: 1.0713x; 1.0713x over previous
#include <cuda_runtime.h>
#include <cstdint>

#define NN 200000
#define KK 27
#define PP 400000
#define CIN 32
#define CMID 64
#define COUT 32

// Scratch: intermediate h [N, CMID] (51.2 MB) — device global, no allocation.
__device__ __align__(16) float g_h[(size_t)NN * CMID];
__device__ int g_is64;

// ---------------------------------------------------------------------------
// Index-width detection (jax may emit int32 despite the int64 request).
// ---------------------------------------------------------------------------
__global__ void detect_idx_kernel(const void* idx) {
    const unsigned int* w = (const unsigned int*)idx;
    int is64 = 1;
    #pragma unroll 1
    for (int i = 0; i < 64; i++) {
        if (w[2 * i + 1] != 0u) { is64 = 0; break; }
    }
    g_is64 = is64;
}

__device__ __forceinline__ long long ld_idx(const void* p, long long i, int is64) {
    if (is64) return ((const long long*)p)[i];
    return (long long)((const int*)p)[i];
}

// ---------------------------------------------------------------------------
// Layer 1: h[out] += feats[in] @ W_in[k].  Warp per pair.
// Lane l owns output cols (2l, 2l+1). W kept in registers (64 regs/lane).
// x read as uniform-address 16B vector loads (broadcast, 1 wavefront each).
// ---------------------------------------------------------------------------
__global__ void __launch_bounds__(256, 2) conv1_kernel(
    const float* __restrict__ feats,
    const void* __restrict__ in_idx, const void* __restrict__ out_idx,
    const float* __restrict__ mask,
    const float* __restrict__ W_in)
{
    const int k = blockIdx.y;
    const int is64 = g_is64;
    const int lane = threadIdx.x & 31;

    // Wa[c] = W[c][2l],  Wb[c] = W[c][2l+1].  64 registers.
    const float* Wk = W_in + (size_t)k * CIN * CMID;
    float Wa[CIN], Wb[CIN];
    #pragma unroll
    for (int c = 0; c < CIN; c++) {
        float2 w = ((const float2*)(Wk + c * CMID))[lane];
        Wa[c] = w.x;
        Wb[c] = w.y;
    }

    const int warp = (blockIdx.x * blockDim.x + threadIdx.x) >> 5;
    const int wstride = (gridDim.x * blockDim.x) >> 5;
    const long long base = (long long)k * PP;

    for (int p = warp; p < PP; p += wstride) {
        const float m = mask[base + p];          // warp-uniform
        if (m <= 0.5f) continue;
        const long long in  = ld_idx(in_idx,  base + p, is64);
        const long long out = ld_idx(out_idx, base + p, is64);

        const float4* xp = (const float4*)(feats + in * CIN);
        float ra = 0.f, rb = 0.f;
        #pragma unroll
        for (int j = 0; j < 8; j++) {            // 8 x uniform LDG.128
            float4 xv = xp[j];                   // c = 4j..4j+3
            ra = fmaf(xv.x, Wa[4 * j + 0], ra);  rb = fmaf(xv.x, Wb[4 * j + 0], rb);
            ra = fmaf(xv.y, Wa[4 * j + 1], ra);  rb = fmaf(xv.y, Wb[4 * j + 1], rb);
            ra = fmaf(xv.z, Wa[4 * j + 2], ra);  rb = fmaf(xv.z, Wb[4 * j + 2], rb);
            ra = fmaf(xv.w, Wa[4 * j + 3], ra);  rb = fmaf(xv.w, Wb[4 * j + 3], rb);
        }
        float* dst = g_h + out * CMID + 2 * lane;      // 8B-aligned
        asm volatile("red.global.add.v2.f32 [%0], {%1, %2};"
                     :: "l"(dst), "f"(ra), "f"(rb) : "memory");
    }
}

// ---------------------------------------------------------------------------
// ReLU in place over h.
// ---------------------------------------------------------------------------
__global__ void relu_kernel() {
    const size_t n4 = (size_t)NN * CMID / 4;
    float4* h4 = (float4*)g_h;
    for (size_t i = (size_t)blockIdx.x * blockDim.x + threadIdx.x; i < n4;
         i += (size_t)gridDim.x * blockDim.x) {
        float4 v = h4[i];
        v.x = fmaxf(v.x, 0.f); v.y = fmaxf(v.y, 0.f);
        v.z = fmaxf(v.z, 0.f); v.w = fmaxf(v.w, 0.f);
        h4[i] = v;
    }
}

// ---------------------------------------------------------------------------
// Layer 2: out[o] += h[in] @ W_out[k].  Warp per pair; lane l owns out col l.
// W[c][l] for c=0..63 in registers (64 regs). Two accumulator chains for ILP.
// ---------------------------------------------------------------------------
__global__ void __launch_bounds__(256, 2) conv2_kernel(
    const void* __restrict__ in_idx, const void* __restrict__ out_idx,
    const float* __restrict__ mask,
    const float* __restrict__ W_out,
    float* __restrict__ outp)
{
    const int k = blockIdx.y;
    const int is64 = g_is64;
    const int lane = threadIdx.x & 31;

    const float* Wk = W_out + (size_t)k * CMID * COUT;
    float Wp[CMID];
    #pragma unroll
    for (int c = 0; c < CMID; c++)               // coalesced across lanes
        Wp[c] = Wk[c * COUT + lane];

    const int warp = (blockIdx.x * blockDim.x + threadIdx.x) >> 5;
    const int wstride = (gridDim.x * blockDim.x) >> 5;
    const long long base = (long long)k * PP;

    for (int p = warp; p < PP; p += wstride) {
        const float m = mask[base + p];
        if (m <= 0.5f) continue;
        const long long in  = ld_idx(in_idx,  base + p, is64);
        const long long out = ld_idx(out_idx, base + p, is64);

        const float4* xp = (const float4*)(g_h + in * CMID);
        float a0 = 0.f, a1 = 0.f;
        #pragma unroll
        for (int j = 0; j < 16; j++) {           // 16 x uniform LDG.128
            float4 xv = xp[j];                   // c = 4j..4j+3
            a0 = fmaf(xv.x, Wp[4 * j + 0], a0);
            a1 = fmaf(xv.y, Wp[4 * j + 1], a1);
            a0 = fmaf(xv.z, Wp[4 * j + 2], a0);
            a1 = fmaf(xv.w, Wp[4 * j + 3], a1);
        }
        atomicAdd(outp + out * COUT + lane, a0 + a1);  // -> RED.E.ADD.F32
    }
}

// ---------------------------------------------------------------------------
// Launch
// ---------------------------------------------------------------------------
extern "C" void kernel_launch(void* const* d_in, const int* in_sizes, int n_in,
                              void* d_out, int out_size) {
    (void)in_sizes; (void)n_in;
    const float* feats   = (const float*)d_in[0];
    const void*  in_idx  = d_in[1];
    const void*  out_idx = d_in[2];
    const float* mask    = (const float*)d_in[3];
    const float* W_in    = (const float*)d_in[4];
    const float* W_out   = (const float*)d_in[5];
    float* outp = (float*)d_out;

    void* h_ptr = nullptr;
    cudaGetSymbolAddress(&h_ptr, g_h);

    detect_idx_kernel<<<1, 1>>>(in_idx);
    cudaMemsetAsync(h_ptr, 0, (size_t)NN * CMID * sizeof(float));
    cudaMemsetAsync(d_out, 0, (size_t)out_size * sizeof(float));

    dim3 grid1(80, KK);
    conv1_kernel<<<grid1, 256>>>(feats, in_idx, out_idx, mask, W_in);

    relu_kernel<<<2048, 256>>>();

    dim3 grid2(80, KK);
    conv2_kernel<<<grid2, 256>>>(in_idx, out_idx, mask, W_out, outp);
}